// round 14
// baseline (speedup 1.0000x reference)
#include <cuda_runtime.h>
#include <cstdint>

#define BB 16
#define HH 1024
#define WW 1024
#define WORDS 32                    // uint32 words per row
#define HW (HH * WW)
#define NPIX (BB * HW)
#define NWORDS (BB * HH * WORDS)

#define NBLK 592                    // 148 SMs x 4 blocks, co-resident
#define NTHR 256
#define NTHREADS (NBLK * NTHR)
#define NWARPS (NTHREADS / 32)

#define ITEMS (BB * HH)             // single-row items (16384)

__device__ unsigned int g_tbits[NWORDS];   // packed target bits (2 MiB)
__device__ unsigned long long g_ecount;
__device__ double g_A;
__device__ double g_B;
__device__ unsigned g_done;
__device__ unsigned g_c1;
__device__ volatile unsigned g_f1;

__device__ __forceinline__ float ex2f(float x) {
    float r; asm("ex2.approx.f32 %0, %1;" : "=f"(r) : "f"(x)); return r;
}

__device__ __forceinline__ void gbar(unsigned* cnt, volatile unsigned* flag) {
    __syncthreads();
    if (threadIdx.x == 0) {
        __threadfence();
        if (atomicAdd(cnt, 1u) == NBLK - 1) *flag = 1u;
        else while (*flag == 0u) __nanosleep(32);
        __threadfence();
    }
    __syncthreads();
}

__global__ void __launch_bounds__(NTHR, 4)
k_fused(const float* __restrict__ s0, const float* __restrict__ s1,
        const int* __restrict__ tgt, float* __restrict__ out) {
    __shared__ float sA[NTHR];
    __shared__ float sB[NTHR];

    const int tid   = threadIdx.x;
    const int lane  = tid & 31;
    const int gtid  = blockIdx.x * NTHR + tid;
    const int gwarp = gtid >> 5;

    // ---------- Phase 1: pack target bits (8 indep. 128B loads/warp-iter) --
    for (int w = gwarp; w < NPIX / 256; w += NWARPS) {
        int base = w * 256;
        int t0 = tgt[base + lane];
        int t1 = tgt[base + 32 + lane];
        int t2 = tgt[base + 64 + lane];
        int t3 = tgt[base + 96 + lane];
        int t4 = tgt[base + 128 + lane];
        int t5 = tgt[base + 160 + lane];
        int t6 = tgt[base + 192 + lane];
        int t7 = tgt[base + 224 + lane];
        unsigned b0 = __ballot_sync(0xffffffffu, t0 != 0);
        unsigned b1 = __ballot_sync(0xffffffffu, t1 != 0);
        unsigned b2 = __ballot_sync(0xffffffffu, t2 != 0);
        unsigned b3 = __ballot_sync(0xffffffffu, t3 != 0);
        unsigned b4 = __ballot_sync(0xffffffffu, t4 != 0);
        unsigned b5 = __ballot_sync(0xffffffffu, t5 != 0);
        unsigned b6 = __ballot_sync(0xffffffffu, t6 != 0);
        unsigned b7 = __ballot_sync(0xffffffffu, t7 != 0);
        if (lane == 0) {
            *(uint4*)&g_tbits[w * 8]     = make_uint4(b0, b1, b2, b3);
            *(uint4*)&g_tbits[w * 8 + 4] = make_uint4(b4, b5, b6, b7);
        }
    }

    // ---------- Phase 2 setup: tensor-split threads ------------------------
    const float LOG2E = 1.4426950408889634f;
    const int tsel = tid >> 7;               // 0 -> s0, 1 -> s1
    const float wgt = tsel ? 0.5f : 1.0f;
    const float* sc = tsel ? s1 : s0;
    const int c8  = (tid & 127) * 8;         // 8-px column within row
    const int wj8 = c8 >> 5;                 // consumed word (0..31)
    const int sh8 = c8 & 31;                 // 0,8,16,24
    const int jw  = ((tid >> 5) & 3) * 8 + (lane & 7);  // word this lane computes

    float accA = 0.f, accB = 0.f;
    unsigned ecnt = 0;

    // per-item body: fused edge-word computation + log2-domain math.
    //   -logp_t/ln2             = sp2(-u) = max(-u,0)+lg2(1+ex2(-|u|))
    //   (0.5*logp_t-logp_o)/ln2 = 0.5*sp2(-u) + u
    auto item_tail = [&](int bimg, int row,
                         float4 a0, float4 a0b, float4 a1, float4 a1b) {
        // ---- edge word for jw, computed by lanes 0..7 of each warp --------
        unsigned eword = 0, Tword = 0;
        if (lane < 8) {
            const unsigned* rb = g_tbits + bimg * HH * WORDS;
            unsigned orL = 0, orM = 0, orR = 0;
            unsigned anL = ~0u, anM = ~0u, anR = ~0u;
            #pragma unroll
            for (int d = -5; d <= 5; ++d) {
                int r = row + d;
                unsigned wl = 0, wm = 0, wr = 0;
                if ((unsigned)r < HH) {
                    const unsigned* pp = rb + r * WORDS;
                    wm = pp[jw];
                    wl = (jw > 0)  ? pp[jw - 1] : 0u;
                    wr = (jw < 31) ? pp[jw + 1] : 0u;
                }
                if (d == 0) Tword = wm;
                orL |= wl; orM |= wm; orR |= wr;
                anL &= wl; anM &= wm; anR &= wr;
            }
            unsigned nL = ~anL, nM = ~anM, nR = ~anR;
            unsigned any1 = orM, any0 = nM;
            #pragma unroll
            for (int s = 1; s <= 5; s++) {
                any1 |= __funnelshift_r(orM, orR, s);
                any1 |= __funnelshift_l(orL, orM, s);
                any0 |= __funnelshift_r(nM, nR, s);
                any0 |= __funnelshift_l(nL, nM, s);
            }
            eword = (Tword & any0) | (~Tword & any1);
            if (tsel == 0) ecnt += __popc(eword);  // each row counted once
        }
        unsigned ew = __shfl_sync(0xffffffffu, eword, lane >> 2) >> sh8;
        unsigned tw = __shfl_sync(0xffffffffu, Tword, lane >> 2) >> sh8;
        unsigned ntw = ~tw;

        float x0[8] = {a0.x, a0.y, a0.z, a0.w, a0b.x, a0b.y, a0b.z, a0b.w};
        float x1[8] = {a1.x, a1.y, a1.z, a1.w, a1b.x, a1b.y, a1b.z, a1b.w};

        #pragma unroll
        for (int k = 0; k < 8; k++) {
            unsigned sflip = (ntw << (31 - k)) & 0x80000000u;
            int      emask = ((int)(ew << (31 - k))) >> 31;
            float d2 = (x1[k] - x0[k]) * LOG2E;
            float u  = __int_as_float(__float_as_int(d2) ^ sflip);
            float z  = ex2f(-fabsf(u));
            float sp = fmaxf(-u, 0.f) + __log2f(1.f + z);
            accA += wgt * sp;
            float Bt = wgt * (0.5f * sp + u);
            accB += __int_as_float(__float_as_int(Bt) & emask);
        }
    };

    // ---------- First item: score loads in flight across the barrier -------
    {
        int it0  = blockIdx.x;               // < ITEMS always
        int bimg = it0 >> 10;
        int row  = it0 & (HH - 1);
        const float* p = sc + (size_t)bimg * 2 * HW + (size_t)row * WW + c8;

        float4 a0  = __ldcs((const float4*)(p));
        float4 a0b = __ldcs((const float4*)(p + 4));
        float4 a1  = __ldcs((const float4*)(p + HW));
        float4 a1b = __ldcs((const float4*)(p + HW + 4));

        gbar(&g_c1, &g_f1);                  // t-bits become valid

        item_tail(bimg, row, a0, a0b, a1, a1b);
    }

    // ---------- Main loop: stream scores + fused edge ----------------------
    for (int it = blockIdx.x + NBLK; it < ITEMS; it += NBLK) {
        int bimg = it >> 10;
        int row  = it & (HH - 1);
        const float* p = sc + (size_t)bimg * 2 * HW + (size_t)row * WW + c8;

        float4 a0  = __ldcs((const float4*)(p));
        float4 a0b = __ldcs((const float4*)(p + 4));
        float4 a1  = __ldcs((const float4*)(p + HW));
        float4 a1b = __ldcs((const float4*)(p + HW + 4));

        item_tail(bimg, row, a0, a0b, a1, a1b);
    }

    // ---------- Block reduction + global accumulation ----------------------
    ecnt = __reduce_add_sync(0xffffffffu, ecnt);

    sA[tid] = accA;
    sB[tid] = accB;
    __syncthreads();
    #pragma unroll
    for (int s = NTHR / 2; s > 0; s >>= 1) {
        if (tid < s) { sA[tid] += sA[tid + s]; sB[tid] += sB[tid + s]; }
        __syncthreads();
    }

    if (lane == 0 && ecnt)
        atomicAdd(&g_ecount, (unsigned long long)ecnt);

    if (tid == 0) {
        atomicAdd(&g_A, (double)sA[0]);
        atomicAdd(&g_B, (double)sB[0]);
        __threadfence();
        unsigned done = atomicAdd(&g_done, 1u);
        if (done == NBLK - 1) {
            const double LN2 = 0.6931471805599453;
            double N = (double)NPIX;
            double a = (double)g_ecount / N;
            if (a > 0.2) a = 0.2;
            out[0] = (float)((g_A + a * g_B) * LN2 / N);
            // reset ALL state for the next graph replay
            g_A = 0.0; g_B = 0.0; g_ecount = 0ull;
            g_c1 = 0u; g_f1 = 0u;
            __threadfence();
            g_done = 0u;
        }
    }
}

// ---------------------------------------------------------------------------
extern "C" void kernel_launch(void* const* d_in, const int* in_sizes, int n_in,
                              void* d_out, int out_size) {
    int ti = 0;
    for (int i = 1; i < n_in; i++)
        if (in_sizes[i] < in_sizes[ti]) ti = i;
    const float* s0 = nullptr;
    const float* s1 = nullptr;
    for (int i = 0; i < n_in; i++) {
        if (i == ti) continue;
        if (!s0) s0 = (const float*)d_in[i];
        else     s1 = (const float*)d_in[i];
    }
    const int* tgt = (const int*)d_in[ti];

    k_fused<<<NBLK, NTHR>>>(s0, s1, tgt, (float*)d_out);
}

// round 16
// speedup vs baseline: 1.5396x; 1.5396x over previous
#include <cuda_runtime.h>
#include <cstdint>

#define BB 16
#define HH 1024
#define WW 1024
#define WORDS 32                    // uint32 words per row
#define HW (HH * WW)
#define NPIX (BB * HW)
#define NWORDS (BB * HH * WORDS)

#define NBLK 740                    // 148 SMs x 5 blocks, co-resident
#define NTHR 256
#define NTHREADS (NBLK * NTHR)
#define NWARPS (NTHREADS / 32)

#define PAIRS (BB * HH / 2)         // 8192 two-row items

__device__ unsigned int g_tbits[NWORDS];   // packed target bits (2 MiB)
__device__ uint2        g_te[NWORDS];      // (tbits, ebits) interleaved (4 MiB)
__device__ unsigned long long g_ecount;
__device__ double g_A;
__device__ double g_B;
__device__ unsigned g_done;
__device__ unsigned g_c1, g_c2;
__device__ volatile unsigned g_f1, g_f2;
__device__ unsigned g_ticket = NBLK;       // work-steal ticket (reset each replay)

__device__ __forceinline__ float ex2f(float x) {
    float r; asm("ex2.approx.f32 %0, %1;" : "=f"(r) : "f"(x)); return r;
}

__device__ __forceinline__ void gbar(unsigned* cnt, volatile unsigned* flag) {
    __syncthreads();
    if (threadIdx.x == 0) {
        __threadfence();
        if (atomicAdd(cnt, 1u) == NBLK - 1) *flag = 1u;
        else while (*flag == 0u) __nanosleep(32);
        __threadfence();
    }
    __syncthreads();
}

__global__ void __launch_bounds__(NTHR, 5)
k_fused(const float* __restrict__ s0, const float* __restrict__ s1,
        const int* __restrict__ tgt, float* __restrict__ out) {
    __shared__ float sA[NTHR];
    __shared__ float sB[NTHR];
    __shared__ int s_it;                     // block's current ticket

    const int tid   = threadIdx.x;
    const int lane  = tid & 31;
    const int gtid  = blockIdx.x * NTHR + tid;
    const int gwarp = gtid >> 5;

    // ---------- Phase 1: pack target bits (8 indep. 128B loads/warp-iter) --
    for (int w = gwarp; w < NPIX / 256; w += NWARPS) {
        int base = w * 256;
        int t0 = __ldcs(&tgt[base + lane]);
        int t1 = __ldcs(&tgt[base + 32 + lane]);
        int t2 = __ldcs(&tgt[base + 64 + lane]);
        int t3 = __ldcs(&tgt[base + 96 + lane]);
        int t4 = __ldcs(&tgt[base + 128 + lane]);
        int t5 = __ldcs(&tgt[base + 160 + lane]);
        int t6 = __ldcs(&tgt[base + 192 + lane]);
        int t7 = __ldcs(&tgt[base + 224 + lane]);
        unsigned b0 = __ballot_sync(0xffffffffu, t0 != 0);
        unsigned b1 = __ballot_sync(0xffffffffu, t1 != 0);
        unsigned b2 = __ballot_sync(0xffffffffu, t2 != 0);
        unsigned b3 = __ballot_sync(0xffffffffu, t3 != 0);
        unsigned b4 = __ballot_sync(0xffffffffu, t4 != 0);
        unsigned b5 = __ballot_sync(0xffffffffu, t5 != 0);
        unsigned b6 = __ballot_sync(0xffffffffu, t6 != 0);
        unsigned b7 = __ballot_sync(0xffffffffu, t7 != 0);
        if (lane == 0) {
            *(uint4*)&g_tbits[w * 8]     = make_uint4(b0, b1, b2, b3);
            *(uint4*)&g_tbits[w * 8 + 4] = make_uint4(b4, b5, b6, b7);
        }
    }

    gbar(&g_c1, &g_f1);

    // ---------- Phase 2: edge words -> g_te (grid-strided) -----------------
    unsigned ecnt = 0;
    for (int idx = gtid; idx < NWORDS; idx += NTHREADS) {
        int j   = idx & (WORDS - 1);
        int row = idx >> 5;                  // b*H + y
        int y   = row & (HH - 1);
        const unsigned* rb = g_tbits + (row - y) * WORDS;

        unsigned orL = 0, orM = 0, orR = 0;
        unsigned anL = ~0u, anM = ~0u, anR = ~0u;
        #pragma unroll
        for (int d = -5; d <= 5; ++d) {
            int r = y + d;
            unsigned wl = 0, wm = 0, wr = 0;
            if ((unsigned)r < HH) {
                const unsigned* p = rb + r * WORDS;
                wm = p[j];
                wl = (j > 0)  ? p[j - 1] : 0u;
                wr = (j < 31) ? p[j + 1] : 0u;
            }
            orL |= wl; orM |= wm; orR |= wr;
            anL &= wl; anM &= wm; anR &= wr;
        }
        unsigned nL = ~anL, nM = ~anM, nR = ~anR;
        unsigned any1 = orM, any0 = nM;
        #pragma unroll
        for (int s = 1; s <= 5; s++) {
            any1 |= __funnelshift_r(orM, orR, s);
            any1 |= __funnelshift_l(orL, orM, s);
            any0 |= __funnelshift_r(nM, nR, s);
            any0 |= __funnelshift_l(nL, nM, s);
        }
        unsigned T = g_tbits[idx];
        unsigned e = (T & any0) | (~T & any1);
        g_te[idx] = make_uint2(T, e);
        ecnt += __popc(e);
    }

    // ---------- Phase 3 setup --------------------------------------------
    const float LOG2E = 1.4426950408889634f;
    const int rsub = tid >> 7;               // row within pair (0/1)
    const int c8   = (tid & 127) * 8;        // 8-px column
    const int wj8  = c8 >> 5;
    const int sh8  = c8 & 31;

    float accA = 0.f, accB = 0.f;

    // ---------- First item (static = blockIdx.x): loads span barrier 2 -----
    {
        int it0 = blockIdx.x;                // < PAIRS always (740 < 8192)
        unsigned bimg = (unsigned)it0 >> 9;
        unsigned row  = ((unsigned)it0 & 511u) * 2u + rsub;
        unsigned widx = (bimg * HH + row) * WORDS + wj8;
        unsigned pixbase = bimg * 2u * HW + row * WW + c8;
        const float* p00 = s0 + pixbase;
        const float* p10 = s1 + pixbase;

        float4 a0  = __ldcs((const float4*)(p00));
        float4 a0b = __ldcs((const float4*)(p00 + 4));
        float4 a1  = __ldcs((const float4*)(p00 + HW));
        float4 a1b = __ldcs((const float4*)(p00 + HW + 4));
        float4 c0  = __ldcs((const float4*)(p10));
        float4 c0b = __ldcs((const float4*)(p10 + 4));
        float4 c1  = __ldcs((const float4*)(p10 + HW));
        float4 c1b = __ldcs((const float4*)(p10 + HW + 4));

        gbar(&g_c2, &g_f2);                  // t/e words become valid

        uint2 te = g_te[widx];
        unsigned tw = te.x >> sh8;
        unsigned ew = te.y >> sh8;
        unsigned ntw = ~tw;

        float x0[8] = {a0.x, a0.y, a0.z, a0.w, a0b.x, a0b.y, a0b.z, a0b.w};
        float x1[8] = {a1.x, a1.y, a1.z, a1.w, a1b.x, a1b.y, a1b.z, a1b.w};
        float y0[8] = {c0.x, c0.y, c0.z, c0.w, c0b.x, c0b.y, c0b.z, c0b.w};
        float y1[8] = {c1.x, c1.y, c1.z, c1.w, c1b.x, c1b.y, c1b.z, c1b.w};

        #pragma unroll
        for (int k = 0; k < 8; k++) {
            unsigned sflip = (ntw << (31 - k)) & 0x80000000u;
            int      emask = ((int)(ew << (31 - k))) >> 31;
            float d2 = (x1[k] - x0[k]) * LOG2E;
            float u  = __int_as_float(__float_as_int(d2) ^ sflip);
            float z  = ex2f(-fabsf(u));
            float sp = fmaxf(-u, 0.f) + __log2f(1.f + z);
            float e2 = (y1[k] - y0[k]) * LOG2E;
            float v  = __int_as_float(__float_as_int(e2) ^ sflip);
            float z2 = ex2f(-fabsf(v));
            float sq = fmaxf(-v, 0.f) + __log2f(1.f + z2);
            accA += sp + 0.5f * sq;
            float Bt = (0.5f * sp + u) + 0.5f * (0.5f * sq + v);
            accB += __int_as_float(__float_as_int(Bt) & emask);
        }
    }

    // ---------- Phase 3: ticket-scheduled streaming ------------------------
    for (;;) {
        if (tid == 0) s_it = (int)atomicAdd(&g_ticket, 1u);
        __syncthreads();
        int it = s_it;
        __syncthreads();
        if (it >= PAIRS) break;

        unsigned bimg = (unsigned)it >> 9;
        unsigned row  = ((unsigned)it & 511u) * 2u + rsub;
        unsigned widx = (bimg * HH + row) * WORDS + wj8;
        unsigned pixbase = bimg * 2u * HW + row * WW + c8;
        const float* p00 = s0 + pixbase;
        const float* p10 = s1 + pixbase;

        float4 a0  = __ldcs((const float4*)(p00));
        float4 a0b = __ldcs((const float4*)(p00 + 4));
        float4 a1  = __ldcs((const float4*)(p00 + HW));
        float4 a1b = __ldcs((const float4*)(p00 + HW + 4));
        float4 c0  = __ldcs((const float4*)(p10));
        float4 c0b = __ldcs((const float4*)(p10 + 4));
        float4 c1  = __ldcs((const float4*)(p10 + HW));
        float4 c1b = __ldcs((const float4*)(p10 + HW + 4));

        uint2 te = g_te[widx];
        unsigned tw = te.x >> sh8;
        unsigned ew = te.y >> sh8;
        unsigned ntw = ~tw;

        float x0[8] = {a0.x, a0.y, a0.z, a0.w, a0b.x, a0b.y, a0b.z, a0b.w};
        float x1[8] = {a1.x, a1.y, a1.z, a1.w, a1b.x, a1b.y, a1b.z, a1b.w};
        float y0[8] = {c0.x, c0.y, c0.z, c0.w, c0b.x, c0b.y, c0b.z, c0b.w};
        float y1[8] = {c1.x, c1.y, c1.z, c1.w, c1b.x, c1b.y, c1b.z, c1b.w};

        #pragma unroll
        for (int k = 0; k < 8; k++) {
            unsigned sflip = (ntw << (31 - k)) & 0x80000000u;
            int      emask = ((int)(ew << (31 - k))) >> 31;

            float d2 = (x1[k] - x0[k]) * LOG2E;
            float u  = __int_as_float(__float_as_int(d2) ^ sflip);
            float z  = ex2f(-fabsf(u));
            float sp = fmaxf(-u, 0.f) + __log2f(1.f + z);

            float e2 = (y1[k] - y0[k]) * LOG2E;
            float v  = __int_as_float(__float_as_int(e2) ^ sflip);
            float z2 = ex2f(-fabsf(v));
            float sq = fmaxf(-v, 0.f) + __log2f(1.f + z2);

            accA += sp + 0.5f * sq;
            float Bt = (0.5f * sp + u) + 0.5f * (0.5f * sq + v);
            accB += __int_as_float(__float_as_int(Bt) & emask);
        }
    }

    // ---------- Block reduction + global accumulation ----------------------
    ecnt = __reduce_add_sync(0xffffffffu, ecnt);

    sA[tid] = accA;
    sB[tid] = accB;
    __syncthreads();
    #pragma unroll
    for (int s = NTHR / 2; s > 0; s >>= 1) {
        if (tid < s) { sA[tid] += sA[tid + s]; sB[tid] += sB[tid + s]; }
        __syncthreads();
    }

    if (lane == 0 && ecnt)
        atomicAdd(&g_ecount, (unsigned long long)ecnt);

    if (tid == 0) {
        atomicAdd(&g_A, (double)sA[0]);
        atomicAdd(&g_B, (double)sB[0]);
        __threadfence();
        unsigned done = atomicAdd(&g_done, 1u);
        if (done == NBLK - 1) {
            const double LN2 = 0.6931471805599453;
            double N = (double)NPIX;
            double a = (double)g_ecount / N;
            if (a > 0.2) a = 0.2;
            out[0] = (float)((g_A + a * g_B) * LN2 / N);
            // reset ALL state for the next graph replay
            g_A = 0.0; g_B = 0.0; g_ecount = 0ull;
            g_c1 = 0u; g_f1 = 0u;
            g_c2 = 0u; g_f2 = 0u;
            g_ticket = NBLK;
            __threadfence();
            g_done = 0u;
        }
    }
}

// ---------------------------------------------------------------------------
extern "C" void kernel_launch(void* const* d_in, const int* in_sizes, int n_in,
                              void* d_out, int out_size) {
    int ti = 0;
    for (int i = 1; i < n_in; i++)
        if (in_sizes[i] < in_sizes[ti]) ti = i;
    const float* s0 = nullptr;
    const float* s1 = nullptr;
    for (int i = 0; i < n_in; i++) {
        if (i == ti) continue;
        if (!s0) s0 = (const float*)d_in[i];
        else     s1 = (const float*)d_in[i];
    }
    const int* tgt = (const int*)d_in[ti];

    k_fused<<<NBLK, NTHR>>>(s0, s1, tgt, (float*)d_out);
}